// round 16
// baseline (speedup 1.0000x reference)
#include <cuda_runtime.h>
#include <cuda.h>
#include <math.h>
#include <stdint.h>

// ---------------------------------------------------------------------------
// VectorQuantizerLinearSoft — R16: R14 GEMMs (known good) + 4-CTA k_soft.
// ---------------------------------------------------------------------------

#if defined(__CUDA_ARCH_FEAT_SM103_ALL) || defined(__CUDA_ARCH_FEAT_SM100_ALL)
#define HAS_TC 1
#else
#define HAS_TC 0
#endif

constexpr int NB = 65536;
constexpr int ND = 256;
constexpr int NK = 1024;

constexpr size_t OFF_Q   = 0;
constexpr size_t OFF_VQ  = 16777216;
constexpr size_t OFF_ENT = 16777217;
constexpr size_t OFF_IDX = 16777218;
constexpr size_t OFF_HQ  = 16842754;   // only 8B-aligned
constexpr size_t OFF_P   = 33619970;   // only 8B-aligned
constexpr size_t OFF_CM  = 100728834;

// Scratch (device globals: no allocations allowed)
__device__ float g_G[(size_t)NB * NK];      // 256MB  lat @ emb^T
__device__ float g_eT[ND * NK];             // emb^T full precision (fallback)
__device__ float g_embI[(size_t)NK * 512];  // emb rows, [hi16|lo16] per 16-col block
__device__ float g_embTI[(size_t)ND * 2048];// emb^T rows, [hi16|lo16]
__device__ float g_ee[NK];                  // ||e_j||^2
__device__ float g_pavg[2048 * NK];         // per-soft-CTA colsums of probs
__device__ float g_pavg2[32 * NK];
__device__ float g_ploss[512];              // per-GEMM2-CTA sum (q-z)^2
__device__ float g_pmind[2048];             // per-soft-CTA sum min dist

// ---------------- generic helpers ----------------
__device__ __forceinline__ void cp16(void* smem, const void* gmem) {
    unsigned s = (unsigned)__cvta_generic_to_shared(smem);
    asm volatile("cp.async.cg.shared.global [%0], [%1], 16;\n" :: "r"(s), "l"(gmem));
}
__device__ __forceinline__ void cp_commit() { asm volatile("cp.async.commit_group;\n"); }
__device__ __forceinline__ void cp_wait1()  { asm volatile("cp.async.wait_group 1;\n"); }
__device__ __forceinline__ void cp_wait0()  { asm volatile("cp.async.wait_group 0;\n"); }

__device__ __forceinline__ float tf32hi(float x) {
    uint32_t u; asm("cvt.rna.tf32.f32 %0, %1;" : "=r"(u) : "f"(x));
    return __uint_as_float(u);
}
__device__ __forceinline__ uint32_t sw128(uint32_t off) { return off ^ ((off >> 3) & 0x70); }

// ---------------- tcgen05 / TMA helpers (accelerated pass only) ------------
#if HAS_TC
__device__ __forceinline__ uint32_t smem_u32(const void* p) {
    uint32_t a;
    asm("{ .reg .u64 t; cvta.to.shared.u64 t, %1; cvt.u32.u64 %0, t; }" : "=r"(a) : "l"(p));
    return a;
}
__device__ __forceinline__ uint32_t elect1() {
    uint32_t p;
    asm volatile("{ .reg .pred p; elect.sync _|p, 0xFFFFFFFF; selp.b32 %0, 1, 0, p; }" : "=r"(p));
    return p;
}
// SW128 K-major smem descriptor (SBO=64, LBO=1, layout SW128, Blackwell v1)
__device__ __forceinline__ uint64_t sdesc(uint32_t addr) {
    return 0x4000404000010000ULL | ((uint64_t)(addr >> 4) & 0x3FFF);
}
// idesc: dtype=F32, atype=btype=TF32(2), N=256, M=128, K-major both
constexpr uint32_t IDESC_TF32_N256 =
    (1u << 4) | (2u << 7) | (2u << 10) | ((256u / 8) << 17) | ((128u / 16) << 24);

__device__ __forceinline__ void mma_tf32(uint32_t d, uint64_t ad, uint64_t bd,
                                         uint32_t idesc, bool en) {
    uint32_t e = en ? 1u : 0u;
    asm volatile(
        "{\n\t.reg .pred p;\n\tsetp.ne.u32 p, %5, 0;\n\t"
        "tcgen05.mma.cta_group::1.kind::tf32 [%0], %1, %2, %3, {%4, %4, %4, %4}, p;\n\t}"
        :: "r"(d), "l"(ad), "l"(bd), "r"(idesc), "r"(0u), "r"(e) : "memory");
}

__device__ __forceinline__ void tma2d(uint32_t dst, const CUtensorMap* map,
                                      int x, int y, uint32_t mbar) {
    asm volatile(
        "cp.async.bulk.tensor.2d.shared::cta.global.tile.mbarrier::complete_tx::bytes "
        "[%0], [%1, {%2, %3}], [%4];"
        :: "r"(dst), "l"(map), "r"(x), "r"(y), "r"(mbar) : "memory");
}

#define FENCE_PROXY()     asm volatile("fence.proxy.async.shared::cta;" ::: "memory")
#define TC_ALLOC(sa, n)   asm volatile("tcgen05.alloc.cta_group::1.sync.aligned.shared::cta.b32 [%0], %1;" :: "r"(sa), "r"(n) : "memory")
#define TC_RELINQ()       asm volatile("tcgen05.relinquish_alloc_permit.cta_group::1.sync.aligned;")
#define TC_DEALLOC(t, n)  asm volatile("tcgen05.dealloc.cta_group::1.sync.aligned.b32 %0, %1;" :: "r"(t), "r"(n))
#define TC_COMMIT(mb)     asm volatile("tcgen05.commit.cta_group::1.mbarrier::arrive::one.shared::cluster.b64 [%0];" :: "r"(mb) : "memory")
#define TC_WAIT_LD()      asm volatile("tcgen05.wait::ld.sync.aligned;" ::: "memory")
#define TC_FENCE_AFTER()  asm volatile("tcgen05.fence::after_thread_sync;" ::: "memory")
#define TC_FENCE_BEFORE() asm volatile("tcgen05.fence::before_thread_sync;" ::: "memory")
#define MBAR_INIT(mb, c)  asm volatile("mbarrier.init.shared.b64 [%0], %1;" :: "r"(mb), "r"(c) : "memory")
#define MBAR_INVAL(mb)    asm volatile("mbarrier.inval.shared.b64 [%0];" :: "r"(mb) : "memory")
#define MBAR_EXPECT(mb, n) asm volatile("mbarrier.arrive.expect_tx.shared.b64 _, [%0], %1;" :: "r"(mb), "r"(n) : "memory")

#define MBAR_WAIT(mb, par) do {                                              \
    uint32_t _m = (mb), _p = (par), _d;                                      \
    asm volatile("{\n\t.reg .pred p;\n\t"                                    \
        "mbarrier.try_wait.parity.acquire.cta.shared::cta.b64 p, [%1], %2;\n\t" \
        "selp.b32 %0, 1, 0, p;\n\t}" : "=r"(_d) : "r"(_m), "r"(_p) : "memory"); \
    if (!_d) {                                                               \
        asm volatile("{\n\t.reg .pred P1;\n\t"                               \
            "WL_%=:\n\t"                                                     \
            "mbarrier.try_wait.parity.acquire.cta.shared::cta.b64 P1, [%0], %1, 0x989680;\n\t" \
            "@P1 bra.uni WD_%=;\n\t"                                         \
            "bra.uni WL_%=;\n\t"                                             \
            "WD_%=:\n\t}" :: "r"(_m), "r"(_p) : "memory");                   \
    }                                                                        \
} while (0)

#define LDTM32(r, a)                                                         \
    asm volatile("tcgen05.ld.sync.aligned.32x32b.x32.b32 "                   \
        "{%0,%1,%2,%3,%4,%5,%6,%7,%8,%9,%10,%11,%12,%13,%14,%15,"            \
        "%16,%17,%18,%19,%20,%21,%22,%23,%24,%25,%26,%27,%28,%29,%30,%31}, [%32];" \
        : "=r"((r)[0]), "=r"((r)[1]), "=r"((r)[2]), "=r"((r)[3]),            \
          "=r"((r)[4]), "=r"((r)[5]), "=r"((r)[6]), "=r"((r)[7]),            \
          "=r"((r)[8]), "=r"((r)[9]), "=r"((r)[10]), "=r"((r)[11]),          \
          "=r"((r)[12]), "=r"((r)[13]), "=r"((r)[14]), "=r"((r)[15]),        \
          "=r"((r)[16]), "=r"((r)[17]), "=r"((r)[18]), "=r"((r)[19]),        \
          "=r"((r)[20]), "=r"((r)[21]), "=r"((r)[22]), "=r"((r)[23]),        \
          "=r"((r)[24]), "=r"((r)[25]), "=r"((r)[26]), "=r"((r)[27]),        \
          "=r"((r)[28]), "=r"((r)[29]), "=r"((r)[30]), "=r"((r)[31])         \
        : "r"(a))
#endif  // HAS_TC

// sub-chunk descriptor offsets (16B units) within a [hi64B|lo64B] 128B row:
// terms: hiA*hiB (2 K-steps), loA*hiB (2), hiA*loB (2)
__device__ __constant__ int c_AO[6] = {0, 2, 4, 6, 0, 2};
__device__ __constant__ int c_BO[6] = {0, 2, 0, 2, 4, 6};

// ---------------- prep: interleaved split tables + row norms ---------------
__global__ void k_prep2(const float* __restrict__ emb) {
    int j = blockIdx.x;  // 0..1023
    int cb = j >> 4, tb = j & 15;
    for (int d = threadIdx.x; d < 256; d += 256) {
        float v = emb[(size_t)j * ND + d];
        float h = tf32hi(v);
        g_eT[(size_t)d * NK + j] = v;
        g_embTI[(size_t)d * 2048 + cb * 32 + tb]      = h;
        g_embTI[(size_t)d * 2048 + cb * 32 + 16 + tb] = __fsub_rn(v, h);
    }
    for (int t = threadIdx.x; t < 512; t += 256) {
        int c = t >> 5, u = t & 31;
        float v = emb[(size_t)j * ND + c * 16 + (u & 15)];
        float h = tf32hi(v);
        g_embI[(size_t)j * 512 + t] = (u < 16) ? h : __fsub_rn(v, h);
    }
}

__global__ void k_ee(const float* __restrict__ emb) {
    int warp = (blockIdx.x * blockDim.x + threadIdx.x) >> 5;
    int lane = threadIdx.x & 31;
    for (int rr = 0; rr < 32; ++rr) {
        int row = warp * 32 + rr;
        float s = 0.f;
#pragma unroll
        for (int k = 0; k < 8; ++k) {
            float v = emb[(size_t)row * ND + lane + 32 * k];
            s = fmaf(v, v, s);
        }
#pragma unroll
        for (int off = 16; off; off >>= 1) s += __shfl_xor_sync(0xffffffffu, s, off);
        if (lane == 0) g_ee[row] = s;
    }
}

// ---------------- profiler window shim (keeps k_gemm1 at launch #4) --------
__global__ void k_nop() {}

// ---------------- GEMM kernels: stage = A(16K) + B(32K) = 48K, 2 stages ----
// smem: [0,4) tmem ptr, [8,24) mma bars, [40,56) tma bars, [80,112) red
constexpr int STG_SZ = 49152;
constexpr int G_SMEM = 1024 + 2 * STG_SZ;   // 99328 per CTA -> 2 CTAs/SM
constexpr int MB_MMA = 8, MB_TMA = 40;

__global__ void __launch_bounds__(256, 2)
k_gemm1(const float* __restrict__ lat,
        const __grid_constant__ CUtensorMap tmB) {
#if HAS_TC
    extern __shared__ char smem[];
    uint32_t sbase = smem_u32(smem);
    const int tid = threadIdx.x, wid = tid >> 5;
    const int row0 = blockIdx.x * 128;

    if (wid == 0) { TC_ALLOC(sbase, 256); TC_RELINQ(); }
    if (tid == 0)
        for (int b = 0; b < 2; ++b) {
            MBAR_INIT(sbase + MB_MMA + b * 8, 1);
            MBAR_INIT(sbase + MB_TMA + b * 8, 1);
        }
    __syncthreads();
    uint32_t tmem;
    asm volatile("ld.shared.b32 %0, [%1];" : "=r"(tmem) : "r"(sbase));

    const float* latb = lat + (size_t)row0 * ND;

    auto prep_load = [&](int gp, float4* v) {
        int c = gp & 15;
#pragma unroll
        for (int it = 0; it < 2; ++it) {
            int t = tid + it * 256;
            int r = t >> 2, c4 = t & 3;
            v[it] = *(const float4*)(latb + (size_t)r * ND + c * 16 + c4 * 4);
        }
    };
    auto prep_storeA = [&](int gp, const float4* v) {
        char* st = smem + 1024 + (gp & 1) * STG_SZ;
#pragma unroll
        for (int it = 0; it < 2; ++it) {
            int t = tid + it * 256;
            int r = t >> 2, c4 = t & 3;
            float4 vv = v[it];
            float4 h = make_float4(tf32hi(vv.x), tf32hi(vv.y), tf32hi(vv.z), tf32hi(vv.w));
            float4 l = make_float4(__fsub_rn(vv.x, h.x), __fsub_rn(vv.y, h.y),
                                   __fsub_rn(vv.z, h.z), __fsub_rn(vv.w, h.w));
            *(float4*)(st + sw128(r * 128 + c4 * 16))      = h;
            *(float4*)(st + sw128(r * 128 + 64 + c4 * 16)) = l;
        }
        FENCE_PROXY();
    };
    auto issue_tma = [&](int gp) {
        if (tid == 0) {
            uint32_t mb = sbase + MB_TMA + (gp & 1) * 8;
            MBAR_EXPECT(mb, 32768u);
            tma2d(sbase + 1024 + (gp & 1) * STG_SZ + 16384, &tmB,
                  (gp & 15) * 32, (gp >> 4) * 256, mb);
        }
    };

    auto epilogue = [&](int q) {
        int wg = tid >> 7, w4 = (tid >> 5) & 3, lane = tid & 31;
        int row = row0 + w4 * 32 + lane;
#pragma unroll 1
        for (int b = 0; b < 4; ++b) {
            uint32_t r[32];
            LDTM32(r, tmem + wg * 128 + b * 32);
            TC_WAIT_LD();
            float4* gp = (float4*)&g_G[(size_t)row * NK + q * 256 + wg * 128 + b * 32];
#pragma unroll
            for (int c4 = 0; c4 < 8; ++c4)
                gp[c4] = make_float4(__uint_as_float(r[c4 * 4 + 0]),
                                     __uint_as_float(r[c4 * 4 + 1]),
                                     __uint_as_float(r[c4 * 4 + 2]),
                                     __uint_as_float(r[c4 * 4 + 3]));
        }
        TC_FENCE_BEFORE();
    };

    {   // prologue: chunks 0, 1
        float4 v[2];
        prep_load(0, v); prep_storeA(0, v); issue_tma(0);
        prep_load(1, v); prep_storeA(1, v); issue_tma(1);
    }

    for (int g = 0; g < 64; ++g) {
        const bool doP = (g + 2 < 64);
        float4 pf[2];
        if (doP) prep_load(g + 2, pf);
        MBAR_WAIT(sbase + MB_TMA + (g & 1) * 8, (uint32_t)((g >> 1) & 1));
        __syncthreads();           // D free (epilogue done) + stage visible
        int c = g & 15;
        if (wid == 0) {
            if (elect1()) {
                uint32_t sa = sbase + 1024 + (g & 1) * STG_SZ;
                uint64_t ad = sdesc(sa);
                uint64_t bd = sdesc(sa + 16384);
#pragma unroll
                for (int i = 0; i < 6; ++i)
                    mma_tf32(tmem, ad + c_AO[i], bd + c_BO[i], IDESC_TF32_N256,
                             (c > 0) || (i > 0));
                TC_COMMIT(sbase + MB_MMA + (g & 1) * 8);
            }
        }
        // 2-stage ring: stage g&1 is reused by chunk g+2 -> must wait own mma
        MBAR_WAIT(sbase + MB_MMA + (g & 1) * 8, (uint32_t)((g >> 1) & 1));
        if (c == 15) {             // pass complete: drain D before next pass
            TC_FENCE_AFTER();
            epilogue(g >> 4);
        }
        if (doP) { prep_storeA(g + 2, pf); issue_tma(g + 2); }
    }
    __syncthreads();
    if (tid == 0)
        for (int b = 0; b < 2; ++b) {
            MBAR_INVAL(sbase + MB_MMA + b * 8);
            MBAR_INVAL(sbase + MB_TMA + b * 8);
        }
    __syncthreads();
    if (wid == 0) TC_DEALLOC(tmem, 256);
#else
    // ---------------- FFMA fallback (R4 GEMM1 structure) ----------------
    extern __shared__ float smf[];
    float* sZ = smf;
    float* sE = smf + 8192;
    const int tid = threadIdx.x, w = tid >> 5, lane = tid & 31;
    const int row0 = blockIdx.x * 128;

    for (int st = 0; st < 4; ++st) {
        const int r0 = row0 + st * 32;
        for (int i = tid; i < 4096; i += 256) cp16(sE + i * 4, g_eT + i * 4);
        cp_commit();
        for (int i = tid; i < 2048; i += 256)
            ((float4*)sZ)[i] = ((const float4*)(lat + (size_t)r0 * ND))[i];
        __syncthreads();

        float acc[4][32];
#pragma unroll
        for (int i = 0; i < 4; ++i)
#pragma unroll
            for (int j = 0; j < 32; ++j) acc[i][j] = 0.f;

#pragma unroll 1
        for (int ch = 0; ch < 16; ++ch) {
            if (ch < 15) {
                const float* src = g_eT + (size_t)(ch + 1) * 16 * NK;
                float* dst = sE + ((ch + 1) & 1) * 16384;
                for (int i = tid; i < 4096; i += 256) cp16(dst + i * 4, src + i * 4);
                cp_commit();
                cp_wait1();
            } else {
                cp_wait0();
            }
            __syncthreads();

            const float* bufp = sE + (ch & 1) * 16384;
            const float* zrow = sZ + (w * 4) * ND + ch * 16;
#pragma unroll 4
            for (int kk = 0; kk < 16; ++kk) {
                float z0 = zrow[kk];
                float z1 = zrow[256 + kk];
                float z2 = zrow[512 + kk];
                float z3 = zrow[768 + kk];
                const float* er = bufp + kk * NK + lane;
#pragma unroll
                for (int j = 0; j < 32; ++j) {
                    float ev = er[j * 32];
                    acc[0][j] = fmaf(z0, ev, acc[0][j]);
                    acc[1][j] = fmaf(z1, ev, acc[1][j]);
                    acc[2][j] = fmaf(z2, ev, acc[2][j]);
                    acc[3][j] = fmaf(z3, ev, acc[3][j]);
                }
            }
            __syncthreads();
        }
#pragma unroll
        for (int i = 0; i < 4; ++i) {
            float* gp = &g_G[(size_t)(r0 + w * 4 + i) * NK];
#pragma unroll
            for (int j = 0; j < 32; ++j) gp[lane + 32 * j] = acc[i][j];
        }
        __syncthreads();
    }
#endif
}

// ---------------- k_soft: 3-scan dist/argmin/softmax, 4 CTAs/SM ------------
__global__ void __launch_bounds__(256, 4)
k_soft(const float* __restrict__ lat, const float* __restrict__ emb,
       float* __restrict__ out) {
    __shared__ float sX[8 * NK];
    __shared__ float s_mind[32];
    __shared__ int   s_idx[32];

    const int cta = blockIdx.x, row0 = cta * 32;
    const int tid = threadIdx.x, w = tid >> 5, lane = tid & 31;

    // init per-warp colsum region (no conflicts: warp w owns sX[w*NK ..])
#pragma unroll
    for (int j = 0; j < 32; ++j) sX[w * NK + lane + 32 * j] = 0.f;

#pragma unroll 1
    for (int i = 0; i < 4; ++i) {
        const int r = row0 + w * 4 + i;
        const float* zr = lat + (size_t)r * ND;
        const float* gr = g_G + (size_t)r * NK;

        float zz = 0.f;
#pragma unroll
        for (int k = 0; k < 8; ++k) { float v = zr[lane + 32 * k]; zz = fmaf(v, v, zz); }
#pragma unroll
        for (int off = 16; off; off >>= 1) zz += __shfl_xor_sync(0xffffffffu, zz, off);

        // ---- scan 1: dmin ----
        float dmin = 3.4e38f;
#pragma unroll 4
        for (int j = 0; j < 32; ++j) {
            float di = __fsub_rn(__fadd_rn(zz, __ldg(&g_ee[lane + 32 * j])),
                                 __fmul_rn(2.0f, gr[lane + 32 * j]));
            dmin = fminf(dmin, di);
        }
#pragma unroll
        for (int off = 16; off; off >>= 1)
            dmin = fminf(dmin, __shfl_xor_sync(0xffffffffu, dmin, off));

        // ---- scan 2: ssum + exact-FFMA argmin refinement ----
        float thr = dmin + 1e-4f;
        float ssum = 0.f;
        float bd = 3.4e38f;
        int   bi = NK;
#pragma unroll 1
        for (int j = 0; j < 32; ++j) {
            float di = __fsub_rn(__fadd_rn(zz, __ldg(&g_ee[lane + 32 * j])),
                                 __fmul_rn(2.0f, gr[lane + 32 * j]));
            ssum += __expf(-10.0f * (di - dmin));
            unsigned m = __ballot_sync(0xffffffffu, di < thr);
            while (m) {
                int src = __ffs(m) - 1;
                m &= m - 1;
                int col = src + 32 * j;
                const float* er = emb + (size_t)col * ND;
                float s = 0.f;
#pragma unroll
                for (int k = 0; k < 8; ++k)
                    s = fmaf(zr[lane + 32 * k], __ldg(&er[lane + 32 * k]), s);
#pragma unroll
                for (int off = 16; off; off >>= 1)
                    s += __shfl_xor_sync(0xffffffffu, s, off);
                float dc = __fsub_rn(__fadd_rn(zz, __ldg(&g_ee[col])),
                                     __fmul_rn(2.0f, s));
                if (dc < bd) { bd = dc; bi = col; }
            }
        }
#pragma unroll
        for (int off = 16; off; off >>= 1) ssum += __shfl_xor_sync(0xffffffffu, ssum, off);
        float rinv = 1.0f / ssum;
        if (lane == 0) { s_mind[w * 4 + i] = bd; s_idx[w * 4 + i] = bi; }

        // ---- scan 3: write P + csum (smem) ----
        float* pout = out + OFF_P + (size_t)r * NK;
#pragma unroll 4
        for (int j = 0; j < 32; ++j) {
            float di = __fsub_rn(__fadd_rn(zz, __ldg(&g_ee[lane + 32 * j])),
                                 __fmul_rn(2.0f, gr[lane + 32 * j]));
            float p = __expf(-10.0f * (di - dmin)) * rinv;
            pout[lane + 32 * j] = p;
            sX[w * NK + lane + 32 * j] += p;
        }
    }
    __syncthreads();

    for (int c = tid; c < NK; c += 256) {
        float s = 0.f;
#pragma unroll
        for (int ww = 0; ww < 8; ++ww) s += sX[ww * NK + c];
        g_pavg[(size_t)cta * NK + c] = s;
    }
    if (tid == 0) {
        float s = 0.f;
        for (int r = 0; r < 32; ++r) s += s_mind[r];
        g_pmind[cta] = s;
    }
    if (tid < 32) out[OFF_IDX + row0 + tid] = (float)s_idx[tid];

    for (int i = tid; i < 32 * ND / 2; i += 256) {
        int r = i >> 7, d2 = i & 127;
        float2 v = ((const float2*)(emb + (size_t)s_idx[r] * ND))[d2];
        ((float2*)(out + OFF_HQ + (size_t)row0 * ND))[i] = v;
    }
}

// ---------------- GEMM2: Q = P @ emb (M=128/CTA, N=256, 64 K-blocks) -------
__global__ void __launch_bounds__(256, 2)
k_gemm2(const float* __restrict__ lat,
        const __grid_constant__ CUtensorMap tmB,
        const float* __restrict__ emb, float* __restrict__ out) {
    (void)emb;
#if HAS_TC
    extern __shared__ char smem[];
    uint32_t sbase = smem_u32(smem);
    const int tid = threadIdx.x, wid = tid >> 5;
    const int row0 = blockIdx.x * 128;

    if (wid == 0) { TC_ALLOC(sbase, 256); TC_RELINQ(); }
    if (tid == 0)
        for (int b = 0; b < 2; ++b) {
            MBAR_INIT(sbase + MB_MMA + b * 8, 1);
            MBAR_INIT(sbase + MB_TMA + b * 8, 1);
        }
    __syncthreads();
    uint32_t tmem;
    asm volatile("ld.shared.b32 %0, [%1];" : "=r"(tmem) : "r"(sbase));

    const float* pbase = out + OFF_P + (size_t)row0 * NK;

    auto prep_load = [&](int gp, float4* v) {
#pragma unroll
        for (int it = 0; it < 2; ++it) {
            int t = tid + it * 256;
            int r = t >> 2, c4 = t & 3;
            const float* src = pbase + (size_t)r * NK + gp * 16 + c4 * 4;
            float2 v01 = *(const float2*)(src);
            float2 v23 = *(const float2*)(src + 2);
            v[it] = make_float4(v01.x, v01.y, v23.x, v23.y);
        }
    };
    auto prep_storeA = [&](int gp, const float4* v) {
        char* st = smem + 1024 + (gp & 1) * STG_SZ;
#pragma unroll
        for (int it = 0; it < 2; ++it) {
            int t = tid + it * 256;
            int r = t >> 2, c4 = t & 3;
            float4 vv = v[it];
            float4 h = make_float4(tf32hi(vv.x), tf32hi(vv.y), tf32hi(vv.z), tf32hi(vv.w));
            float4 l = make_float4(__fsub_rn(vv.x, h.x), __fsub_rn(vv.y, h.y),
                                   __fsub_rn(vv.z, h.z), __fsub_rn(vv.w, h.w));
            *(float4*)(st + sw128(r * 128 + c4 * 16))      = h;
            *(float4*)(st + sw128(r * 128 + 64 + c4 * 16)) = l;
        }
        FENCE_PROXY();
    };
    auto issue_tma = [&](int gp) {
        if (tid == 0) {
            uint32_t mb = sbase + MB_TMA + (gp & 1) * 8;
            MBAR_EXPECT(mb, 32768u);
            tma2d(sbase + 1024 + (gp & 1) * STG_SZ + 16384, &tmB,
                  gp * 32, 0, mb);
        }
    };

    {   // prologue
        float4 v[2];
        prep_load(0, v); prep_storeA(0, v); issue_tma(0);
        prep_load(1, v); prep_storeA(1, v); issue_tma(1);
    }

    for (int g = 0; g < 64; ++g) {
        const bool doP = (g + 2 < 64);
        float4 pf[2];
        if (doP) prep_load(g + 2, pf);
        MBAR_WAIT(sbase + MB_TMA + (g & 1) * 8, (uint32_t)((g >> 1) & 1));
        __syncthreads();
        if (wid == 0) {
            if (elect1()) {
                uint32_t sa = sbase + 1024 + (g & 1) * STG_SZ;
                uint64_t ad = sdesc(sa);
                uint64_t bd = sdesc(sa + 16384);
#pragma unroll
                for (int i = 0; i < 6; ++i)
                    mma_tf32(tmem, ad + c_AO[i], bd + c_BO[i], IDESC_TF32_N256,
                             (g > 0) || (i > 0));
                TC_COMMIT(sbase + MB_MMA + (g & 1) * 8);
            }
        }
        MBAR_WAIT(sbase + MB_MMA + (g & 1) * 8, (uint32_t)((g >> 1) & 1));
        if (doP) { prep_storeA(g + 2, pf); issue_tma(g + 2); }
    }
    TC_FENCE_AFTER();

    // epilogue: D[128 lanes][256 cols] -> q, loss partial
    {
        int wg = tid >> 7, w4 = (tid >> 5) & 3, lane = tid & 31;
        int row = row0 + w4 * 32 + lane;
        float lp = 0.f;
#pragma unroll 1
        for (int b = 0; b < 4; ++b) {
            uint32_t r[32];
            LDTM32(r, tmem + wg * 128 + b * 32);
            TC_WAIT_LD();
            int cb = wg * 128 + b * 32;
            float4* qp = (float4*)(out + OFF_Q + (size_t)row * ND + cb);
            const float4* lt = (const float4*)(lat + (size_t)row * ND + cb);
#pragma unroll
            for (int c4 = 0; c4 < 8; ++c4) {
                float4 q = make_float4(__uint_as_float(r[c4 * 4 + 0]),
                                       __uint_as_float(r[c4 * 4 + 1]),
                                       __uint_as_float(r[c4 * 4 + 2]),
                                       __uint_as_float(r[c4 * 4 + 3]));
                float4 l = lt[c4];
                qp[c4] = q;
                float d0 = q.x - l.x, d1 = q.y - l.y, d2 = q.z - l.z, d3 = q.w - l.w;
                lp = fmaf(d0, d0, lp); lp = fmaf(d1, d1, lp);
                lp = fmaf(d2, d2, lp); lp = fmaf(d3, d3, lp);
            }
        }
        TC_FENCE_BEFORE();
#pragma unroll
        for (int off = 16; off; off >>= 1) lp += __shfl_xor_sync(0xffffffffu, lp, off);
        float* red = (float*)(smem + 80);
        if ((tid & 31) == 0) red[tid >> 5] = lp;
        __syncthreads();
        if (tid == 0) {
            float s = 0.f;
            for (int ww = 0; ww < 8; ++ww) s += red[ww];
            g_ploss[blockIdx.x] = s;
        }
    }
    if (tid == 0)
        for (int b = 0; b < 2; ++b) {
            MBAR_INVAL(sbase + MB_MMA + b * 8);
            MBAR_INVAL(sbase + MB_TMA + b * 8);
        }
    __syncthreads();
    if (wid == 0) TC_DEALLOC(tmem, 256);
#else
    // ---------------- FFMA fallback (R4 GEMM2 structure) ----------------
    extern __shared__ float smf[];
    float* sE  = smf;
    float* sPb = smf + 16384;
    __shared__ float red8[8];
    const int tid = threadIdx.x, w = tid >> 5, lane = tid & 31;
    const int row0 = blockIdx.x * 128;
    float lsum = 0.f;

    for (int st = 0; st < 4; ++st) {
        const int r0 = row0 + st * 32;
        const float* pbase = out + OFF_P + (size_t)r0 * NK;

        float qacc[4][8];
#pragma unroll
        for (int i = 0; i < 4; ++i)
#pragma unroll
            for (int m = 0; m < 8; ++m) qacc[i][m] = 0.f;

        for (int i = tid; i < 2048; i += 256) cp16(sE + i * 4, emb + i * 4);
        cp_commit();

#pragma unroll 1
        for (int ch = 0; ch < 32; ++ch) {
            if (ch < 31) {
                const float* src = emb + (size_t)(ch + 1) * 32 * ND;
                float* dst = sE + ((ch + 1) & 1) * 8192;
                for (int i = tid; i < 2048; i += 256) cp16(dst + i * 4, src + i * 4);
                cp_commit();
                cp_wait1();
            } else {
                cp_wait0();
            }
            __syncthreads();
            for (int i = tid; i < 1024; i += 256) {
                int r = i >> 5, c = i & 31;
                sPb[i] = pbase[(size_t)r * NK + ch * 32 + c];
            }
            __syncthreads();

            const float* bp = sE + (ch & 1) * 8192;
#pragma unroll 4
            for (int c = 0; c < 32; ++c) {
                float p0 = sPb[(w * 4 + 0) * 32 + c];
                float p1 = sPb[(w * 4 + 1) * 32 + c];
                float p2 = sPb[(w * 4 + 2) * 32 + c];
                float p3 = sPb[(w * 4 + 3) * 32 + c];
                const float* er = bp + c * ND + lane;
#pragma unroll
                for (int m = 0; m < 8; ++m) {
                    float ev = er[32 * m];
                    qacc[0][m] = fmaf(p0, ev, qacc[0][m]);
                    qacc[1][m] = fmaf(p1, ev, qacc[1][m]);
                    qacc[2][m] = fmaf(p2, ev, qacc[2][m]);
                    qacc[3][m] = fmaf(p3, ev, qacc[3][m]);
                }
            }
            __syncthreads();
        }
#pragma unroll
        for (int i = 0; i < 4; ++i) {
            int row = r0 + w * 4 + i;
#pragma unroll
            for (int m = 0; m < 8; ++m) {
                int d = lane + 32 * m;
                float qv = qacc[i][m];
                out[OFF_Q + (size_t)row * ND + d] = qv;
                float dz = qv - lat[(size_t)row * ND + d];
                lsum = fmaf(dz, dz, lsum);
            }
        }
        __syncthreads();
    }
#pragma unroll
    for (int off = 16; off; off >>= 1) lsum += __shfl_xor_sync(0xffffffffu, lsum, off);
    if (lane == 0) red8[w] = lsum;
    __syncthreads();
    if (tid == 0) {
        float s = 0.f;
        for (int ww = 0; ww < 8; ++ww) s += red8[ww];
        g_ploss[blockIdx.x] = s;
    }
#endif
}

// ---------------- stage-2 avg_probs reduction ----------------
__global__ void k_red() {
    int g = blockIdx.x;
    for (int c = threadIdx.x; c < NK; c += 256) {
        float s = 0.f;
        for (int r = 0; r < 64; ++r) s += g_pavg[(size_t)(g * 64 + r) * NK + c];
        g_pavg2[g * NK + c] = s;
    }
}

// ---------------- finalize scalars ----------------
__global__ void k_fin(float* __restrict__ out) {
    __shared__ float red[1024];
    int t = threadIdx.x;

    float a = 0.f;
    for (int gg = 0; gg < 32; ++gg) a += g_pavg2[gg * NK + t];
    a *= (1.0f / 65536.0f);
    red[t] = -a * logf(a + 1e-10f);
    __syncthreads();
    for (int s = 512; s; s >>= 1) { if (t < s) red[t] += red[t + s]; __syncthreads(); }
    float ent = red[0];
    __syncthreads();

    red[t] = (t < 512) ? g_ploss[t] : 0.f;
    __syncthreads();
    for (int s = 512; s; s >>= 1) { if (t < s) red[t] += red[t + s]; __syncthreads(); }
    float mse = red[0] * (1.0f / 16777216.0f);
    float vq  = __fadd_rn(__fmul_rn(mse, 0.25f), mse);
    __syncthreads();

    red[t] = g_pmind[t] + g_pmind[t + 1024];
    __syncthreads();
    for (int s = 512; s; s >>= 1) { if (t < s) red[t] += red[t + s]; __syncthreads(); }
    float cm = red[0] * (1.0f / 65536.0f);

    if (t == 0) {
        out[OFF_VQ]  = vq;
        out[OFF_ENT] = ent;
        out[OFF_CM]  = cm;
    }
}

// ---------------- host: tensormap construction ----------------
typedef CUresult (*EncodeFn)(CUtensorMap*, CUtensorMapDataType, cuuint32_t,
                             void*, const cuuint64_t*, const cuuint64_t*,
                             const cuuint32_t*, const cuuint32_t*,
                             CUtensorMapInterleave, CUtensorMapSwizzle,
                             CUtensorMapL2promotion, CUtensorMapFloatOOBfill);

static void make_map(EncodeFn enc, CUtensorMap* m, void* ptr,
                     unsigned long long d0, unsigned long long d1,
                     unsigned long long stride_bytes) {
    cuuint64_t dims[2] = {d0, d1};
    cuuint64_t str[1]  = {stride_bytes};
    cuuint32_t box[2]  = {32u, 256u};
    cuuint32_t es[2]   = {1u, 1u};
    enc(m, CU_TENSOR_MAP_DATA_TYPE_FLOAT32, 2, ptr, dims, str, box, es,
        CU_TENSOR_MAP_INTERLEAVE_NONE, CU_TENSOR_MAP_SWIZZLE_128B,
        CU_TENSOR_MAP_L2_PROMOTION_L2_128B, CU_TENSOR_MAP_FLOAT_OOB_FILL_NONE);
}

// ---------------- launch ----------------
extern "C" void kernel_launch(void* const* d_in, const int* in_sizes, int n_in,
                              void* d_out, int out_size) {
    const float* lat = (const float*)d_in[0];
    const float* emb = (const float*)d_in[1];
    float* out = (float*)d_out;

    void* fp = nullptr;
    cudaDriverEntryPointQueryResult qr;
    cudaGetDriverEntryPoint("cuTensorMapEncodeTiled", &fp, cudaEnableDefault, &qr);
    EncodeFn enc = (EncodeFn)fp;

    void *pEmbI = nullptr, *pEmbTI = nullptr;
    cudaGetSymbolAddress(&pEmbI, g_embI);
    cudaGetSymbolAddress(&pEmbTI, g_embTI);

    CUtensorMap m1, m2;
    make_map(enc, &m1, pEmbI, 512, 1024, 512ull * 4ull);
    make_map(enc, &m2, pEmbTI, 2048, 256, 2048ull * 4ull);

    cudaFuncSetAttribute(k_gemm1, cudaFuncAttributeMaxDynamicSharedMemorySize, G_SMEM);
    cudaFuncSetAttribute(k_gemm2, cudaFuncAttributeMaxDynamicSharedMemorySize, G_SMEM);

    k_prep2<<<1024, 256>>>(emb);
    k_ee<<<4, 256>>>(emb);
    k_nop<<<1, 32>>>();                 // keeps k_gemm1 at launch #4 for ncu
    k_gemm1<<<512, 256, G_SMEM>>>(lat, m1);
    k_soft<<<2048, 256>>>(lat, emb, out);
    k_gemm2<<<512, 256, G_SMEM>>>(lat, m2, emb, out);
    k_red<<<32, 256>>>();
    k_fin<<<1, 1024>>>(out);
}

// round 17
// speedup vs baseline: 1.2519x; 1.2519x over previous
#include <cuda_runtime.h>
#include <cuda.h>
#include <math.h>
#include <stdint.h>

// ---------------------------------------------------------------------------
// VectorQuantizerLinearSoft — R17: R14 GEMMs + vectorized single-scan k_soft.
// ---------------------------------------------------------------------------

#if defined(__CUDA_ARCH_FEAT_SM103_ALL) || defined(__CUDA_ARCH_FEAT_SM100_ALL)
#define HAS_TC 1
#else
#define HAS_TC 0
#endif

constexpr int NB = 65536;
constexpr int ND = 256;
constexpr int NK = 1024;

constexpr size_t OFF_Q   = 0;
constexpr size_t OFF_VQ  = 16777216;
constexpr size_t OFF_ENT = 16777217;
constexpr size_t OFF_IDX = 16777218;
constexpr size_t OFF_HQ  = 16842754;   // only 8B-aligned
constexpr size_t OFF_P   = 33619970;   // only 8B-aligned
constexpr size_t OFF_CM  = 100728834;

// Scratch (device globals: no allocations allowed)
__device__ float g_G[(size_t)NB * NK];      // 256MB  lat @ emb^T
__device__ float g_eT[ND * NK];             // emb^T full precision (fallback)
__device__ float g_embI[(size_t)NK * 512];  // emb rows, [hi16|lo16] per 16-col block
__device__ float g_embTI[(size_t)ND * 2048];// emb^T rows, [hi16|lo16]
__device__ float g_ee[NK];                  // ||e_j||^2
__device__ float g_pavg[2048 * NK];         // per-soft-CTA colsums of probs
__device__ float g_pavg2[32 * NK];
__device__ float g_ploss[512];              // per-GEMM2-CTA sum (q-z)^2
__device__ float g_pmind[2048];             // per-soft-CTA sum min dist

// ---------------- generic helpers ----------------
__device__ __forceinline__ void cp16(void* smem, const void* gmem) {
    unsigned s = (unsigned)__cvta_generic_to_shared(smem);
    asm volatile("cp.async.cg.shared.global [%0], [%1], 16;\n" :: "r"(s), "l"(gmem));
}
__device__ __forceinline__ void cp_commit() { asm volatile("cp.async.commit_group;\n"); }
__device__ __forceinline__ void cp_wait1()  { asm volatile("cp.async.wait_group 1;\n"); }
__device__ __forceinline__ void cp_wait0()  { asm volatile("cp.async.wait_group 0;\n"); }

__device__ __forceinline__ float tf32hi(float x) {
    uint32_t u; asm("cvt.rna.tf32.f32 %0, %1;" : "=r"(u) : "f"(x));
    return __uint_as_float(u);
}
__device__ __forceinline__ uint32_t sw128(uint32_t off) { return off ^ ((off >> 3) & 0x70); }

// ---------------- tcgen05 / TMA helpers (accelerated pass only) ------------
#if HAS_TC
__device__ __forceinline__ uint32_t smem_u32(const void* p) {
    uint32_t a;
    asm("{ .reg .u64 t; cvta.to.shared.u64 t, %1; cvt.u32.u64 %0, t; }" : "=r"(a) : "l"(p));
    return a;
}
__device__ __forceinline__ uint32_t elect1() {
    uint32_t p;
    asm volatile("{ .reg .pred p; elect.sync _|p, 0xFFFFFFFF; selp.b32 %0, 1, 0, p; }" : "=r"(p));
    return p;
}
// SW128 K-major smem descriptor (SBO=64, LBO=1, layout SW128, Blackwell v1)
__device__ __forceinline__ uint64_t sdesc(uint32_t addr) {
    return 0x4000404000010000ULL | ((uint64_t)(addr >> 4) & 0x3FFF);
}
// idesc: dtype=F32, atype=btype=TF32(2), N=256, M=128, K-major both
constexpr uint32_t IDESC_TF32_N256 =
    (1u << 4) | (2u << 7) | (2u << 10) | ((256u / 8) << 17) | ((128u / 16) << 24);

__device__ __forceinline__ void mma_tf32(uint32_t d, uint64_t ad, uint64_t bd,
                                         uint32_t idesc, bool en) {
    uint32_t e = en ? 1u : 0u;
    asm volatile(
        "{\n\t.reg .pred p;\n\tsetp.ne.u32 p, %5, 0;\n\t"
        "tcgen05.mma.cta_group::1.kind::tf32 [%0], %1, %2, %3, {%4, %4, %4, %4}, p;\n\t}"
        :: "r"(d), "l"(ad), "l"(bd), "r"(idesc), "r"(0u), "r"(e) : "memory");
}

__device__ __forceinline__ void tma2d(uint32_t dst, const CUtensorMap* map,
                                      int x, int y, uint32_t mbar) {
    asm volatile(
        "cp.async.bulk.tensor.2d.shared::cta.global.tile.mbarrier::complete_tx::bytes "
        "[%0], [%1, {%2, %3}], [%4];"
        :: "r"(dst), "l"(map), "r"(x), "r"(y), "r"(mbar) : "memory");
}

#define FENCE_PROXY()     asm volatile("fence.proxy.async.shared::cta;" ::: "memory")
#define TC_ALLOC(sa, n)   asm volatile("tcgen05.alloc.cta_group::1.sync.aligned.shared::cta.b32 [%0], %1;" :: "r"(sa), "r"(n) : "memory")
#define TC_RELINQ()       asm volatile("tcgen05.relinquish_alloc_permit.cta_group::1.sync.aligned;")
#define TC_DEALLOC(t, n)  asm volatile("tcgen05.dealloc.cta_group::1.sync.aligned.b32 %0, %1;" :: "r"(t), "r"(n))
#define TC_COMMIT(mb)     asm volatile("tcgen05.commit.cta_group::1.mbarrier::arrive::one.shared::cluster.b64 [%0];" :: "r"(mb) : "memory")
#define TC_WAIT_LD()      asm volatile("tcgen05.wait::ld.sync.aligned;" ::: "memory")
#define TC_FENCE_AFTER()  asm volatile("tcgen05.fence::after_thread_sync;" ::: "memory")
#define TC_FENCE_BEFORE() asm volatile("tcgen05.fence::before_thread_sync;" ::: "memory")
#define MBAR_INIT(mb, c)  asm volatile("mbarrier.init.shared.b64 [%0], %1;" :: "r"(mb), "r"(c) : "memory")
#define MBAR_INVAL(mb)    asm volatile("mbarrier.inval.shared.b64 [%0];" :: "r"(mb) : "memory")
#define MBAR_EXPECT(mb, n) asm volatile("mbarrier.arrive.expect_tx.shared.b64 _, [%0], %1;" :: "r"(mb), "r"(n) : "memory")

#define MBAR_WAIT(mb, par) do {                                              \
    uint32_t _m = (mb), _p = (par), _d;                                      \
    asm volatile("{\n\t.reg .pred p;\n\t"                                    \
        "mbarrier.try_wait.parity.acquire.cta.shared::cta.b64 p, [%1], %2;\n\t" \
        "selp.b32 %0, 1, 0, p;\n\t}" : "=r"(_d) : "r"(_m), "r"(_p) : "memory"); \
    if (!_d) {                                                               \
        asm volatile("{\n\t.reg .pred P1;\n\t"                               \
            "WL_%=:\n\t"                                                     \
            "mbarrier.try_wait.parity.acquire.cta.shared::cta.b64 P1, [%0], %1, 0x989680;\n\t" \
            "@P1 bra.uni WD_%=;\n\t"                                         \
            "bra.uni WL_%=;\n\t"                                             \
            "WD_%=:\n\t}" :: "r"(_m), "r"(_p) : "memory");                   \
    }                                                                        \
} while (0)

#define LDTM32(r, a)                                                         \
    asm volatile("tcgen05.ld.sync.aligned.32x32b.x32.b32 "                   \
        "{%0,%1,%2,%3,%4,%5,%6,%7,%8,%9,%10,%11,%12,%13,%14,%15,"            \
        "%16,%17,%18,%19,%20,%21,%22,%23,%24,%25,%26,%27,%28,%29,%30,%31}, [%32];" \
        : "=r"((r)[0]), "=r"((r)[1]), "=r"((r)[2]), "=r"((r)[3]),            \
          "=r"((r)[4]), "=r"((r)[5]), "=r"((r)[6]), "=r"((r)[7]),            \
          "=r"((r)[8]), "=r"((r)[9]), "=r"((r)[10]), "=r"((r)[11]),          \
          "=r"((r)[12]), "=r"((r)[13]), "=r"((r)[14]), "=r"((r)[15]),        \
          "=r"((r)[16]), "=r"((r)[17]), "=r"((r)[18]), "=r"((r)[19]),        \
          "=r"((r)[20]), "=r"((r)[21]), "=r"((r)[22]), "=r"((r)[23]),        \
          "=r"((r)[24]), "=r"((r)[25]), "=r"((r)[26]), "=r"((r)[27]),        \
          "=r"((r)[28]), "=r"((r)[29]), "=r"((r)[30]), "=r"((r)[31])         \
        : "r"(a))
#endif  // HAS_TC

// sub-chunk descriptor offsets (16B units) within a [hi64B|lo64B] 128B row:
// terms: hiA*hiB (2 K-steps), loA*hiB (2), hiA*loB (2)
__device__ __constant__ int c_AO[6] = {0, 2, 4, 6, 0, 2};
__device__ __constant__ int c_BO[6] = {0, 2, 0, 2, 4, 6};

// ---------------- prep: interleaved split tables + row norms ---------------
__global__ void k_prep2(const float* __restrict__ emb) {
    int j = blockIdx.x;  // 0..1023
    int cb = j >> 4, tb = j & 15;
    for (int d = threadIdx.x; d < 256; d += 256) {
        float v = emb[(size_t)j * ND + d];
        float h = tf32hi(v);
        g_eT[(size_t)d * NK + j] = v;
        g_embTI[(size_t)d * 2048 + cb * 32 + tb]      = h;
        g_embTI[(size_t)d * 2048 + cb * 32 + 16 + tb] = __fsub_rn(v, h);
    }
    for (int t = threadIdx.x; t < 512; t += 256) {
        int c = t >> 5, u = t & 31;
        float v = emb[(size_t)j * ND + c * 16 + (u & 15)];
        float h = tf32hi(v);
        g_embI[(size_t)j * 512 + t] = (u < 16) ? h : __fsub_rn(v, h);
    }
}

__global__ void k_ee(const float* __restrict__ emb) {
    int warp = (blockIdx.x * blockDim.x + threadIdx.x) >> 5;
    int lane = threadIdx.x & 31;
    for (int rr = 0; rr < 32; ++rr) {
        int row = warp * 32 + rr;
        float s = 0.f;
#pragma unroll
        for (int k = 0; k < 8; ++k) {
            float v = emb[(size_t)row * ND + lane + 32 * k];
            s = fmaf(v, v, s);
        }
#pragma unroll
        for (int off = 16; off; off >>= 1) s += __shfl_xor_sync(0xffffffffu, s, off);
        if (lane == 0) g_ee[row] = s;
    }
}

// ---------------- profiler window shim (keeps k_gemm1 at launch #4) --------
__global__ void k_nop() {}

// ---------------- GEMM kernels: stage = A(16K) + B(32K) = 48K, 2 stages ----
// smem: [0,4) tmem ptr, [8,24) mma bars, [40,56) tma bars, [80,112) red
constexpr int STG_SZ = 49152;
constexpr int G_SMEM = 1024 + 2 * STG_SZ;   // 99328 per CTA -> 2 CTAs/SM
constexpr int MB_MMA = 8, MB_TMA = 40;

__global__ void __launch_bounds__(256, 2)
k_gemm1(const float* __restrict__ lat,
        const __grid_constant__ CUtensorMap tmB) {
#if HAS_TC
    extern __shared__ char smem[];
    uint32_t sbase = smem_u32(smem);
    const int tid = threadIdx.x, wid = tid >> 5;
    const int row0 = blockIdx.x * 128;

    if (wid == 0) { TC_ALLOC(sbase, 256); TC_RELINQ(); }
    if (tid == 0)
        for (int b = 0; b < 2; ++b) {
            MBAR_INIT(sbase + MB_MMA + b * 8, 1);
            MBAR_INIT(sbase + MB_TMA + b * 8, 1);
        }
    __syncthreads();
    uint32_t tmem;
    asm volatile("ld.shared.b32 %0, [%1];" : "=r"(tmem) : "r"(sbase));

    const float* latb = lat + (size_t)row0 * ND;

    auto prep_load = [&](int gp, float4* v) {
        int c = gp & 15;
#pragma unroll
        for (int it = 0; it < 2; ++it) {
            int t = tid + it * 256;
            int r = t >> 2, c4 = t & 3;
            v[it] = *(const float4*)(latb + (size_t)r * ND + c * 16 + c4 * 4);
        }
    };
    auto prep_storeA = [&](int gp, const float4* v) {
        char* st = smem + 1024 + (gp & 1) * STG_SZ;
#pragma unroll
        for (int it = 0; it < 2; ++it) {
            int t = tid + it * 256;
            int r = t >> 2, c4 = t & 3;
            float4 vv = v[it];
            float4 h = make_float4(tf32hi(vv.x), tf32hi(vv.y), tf32hi(vv.z), tf32hi(vv.w));
            float4 l = make_float4(__fsub_rn(vv.x, h.x), __fsub_rn(vv.y, h.y),
                                   __fsub_rn(vv.z, h.z), __fsub_rn(vv.w, h.w));
            *(float4*)(st + sw128(r * 128 + c4 * 16))      = h;
            *(float4*)(st + sw128(r * 128 + 64 + c4 * 16)) = l;
        }
        FENCE_PROXY();
    };
    auto issue_tma = [&](int gp) {
        if (tid == 0) {
            uint32_t mb = sbase + MB_TMA + (gp & 1) * 8;
            MBAR_EXPECT(mb, 32768u);
            tma2d(sbase + 1024 + (gp & 1) * STG_SZ + 16384, &tmB,
                  (gp & 15) * 32, (gp >> 4) * 256, mb);
        }
    };

    auto epilogue = [&](int q) {
        int wg = tid >> 7, w4 = (tid >> 5) & 3, lane = tid & 31;
        int row = row0 + w4 * 32 + lane;
#pragma unroll 1
        for (int b = 0; b < 4; ++b) {
            uint32_t r[32];
            LDTM32(r, tmem + wg * 128 + b * 32);
            TC_WAIT_LD();
            float4* gp = (float4*)&g_G[(size_t)row * NK + q * 256 + wg * 128 + b * 32];
#pragma unroll
            for (int c4 = 0; c4 < 8; ++c4)
                gp[c4] = make_float4(__uint_as_float(r[c4 * 4 + 0]),
                                     __uint_as_float(r[c4 * 4 + 1]),
                                     __uint_as_float(r[c4 * 4 + 2]),
                                     __uint_as_float(r[c4 * 4 + 3]));
        }
        TC_FENCE_BEFORE();
    };

    {   // prologue: chunks 0, 1
        float4 v[2];
        prep_load(0, v); prep_storeA(0, v); issue_tma(0);
        prep_load(1, v); prep_storeA(1, v); issue_tma(1);
    }

    for (int g = 0; g < 64; ++g) {
        const bool doP = (g + 2 < 64);
        float4 pf[2];
        if (doP) prep_load(g + 2, pf);
        MBAR_WAIT(sbase + MB_TMA + (g & 1) * 8, (uint32_t)((g >> 1) & 1));
        __syncthreads();           // D free (epilogue done) + stage visible
        int c = g & 15;
        if (wid == 0) {
            if (elect1()) {
                uint32_t sa = sbase + 1024 + (g & 1) * STG_SZ;
                uint64_t ad = sdesc(sa);
                uint64_t bd = sdesc(sa + 16384);
#pragma unroll
                for (int i = 0; i < 6; ++i)
                    mma_tf32(tmem, ad + c_AO[i], bd + c_BO[i], IDESC_TF32_N256,
                             (c > 0) || (i > 0));
                TC_COMMIT(sbase + MB_MMA + (g & 1) * 8);
            }
        }
        // 2-stage ring: stage g&1 is reused by chunk g+2 -> must wait own mma
        MBAR_WAIT(sbase + MB_MMA + (g & 1) * 8, (uint32_t)((g >> 1) & 1));
        if (c == 15) {             // pass complete: drain D before next pass
            TC_FENCE_AFTER();
            epilogue(g >> 4);
        }
        if (doP) { prep_storeA(g + 2, pf); issue_tma(g + 2); }
    }
    __syncthreads();
    if (tid == 0)
        for (int b = 0; b < 2; ++b) {
            MBAR_INVAL(sbase + MB_MMA + b * 8);
            MBAR_INVAL(sbase + MB_TMA + b * 8);
        }
    __syncthreads();
    if (wid == 0) TC_DEALLOC(tmem, 256);
#else
    // ---------------- FFMA fallback (R4 GEMM1 structure) ----------------
    extern __shared__ float smf[];
    float* sZ = smf;
    float* sE = smf + 8192;
    const int tid = threadIdx.x, w = tid >> 5, lane = tid & 31;
    const int row0 = blockIdx.x * 128;

    for (int st = 0; st < 4; ++st) {
        const int r0 = row0 + st * 32;
        for (int i = tid; i < 4096; i += 256) cp16(sE + i * 4, g_eT + i * 4);
        cp_commit();
        for (int i = tid; i < 2048; i += 256)
            ((float4*)sZ)[i] = ((const float4*)(lat + (size_t)r0 * ND))[i];
        __syncthreads();

        float acc[4][32];
#pragma unroll
        for (int i = 0; i < 4; ++i)
#pragma unroll
            for (int j = 0; j < 32; ++j) acc[i][j] = 0.f;

#pragma unroll 1
        for (int ch = 0; ch < 16; ++ch) {
            if (ch < 15) {
                const float* src = g_eT + (size_t)(ch + 1) * 16 * NK;
                float* dst = sE + ((ch + 1) & 1) * 16384;
                for (int i = tid; i < 4096; i += 256) cp16(dst + i * 4, src + i * 4);
                cp_commit();
                cp_wait1();
            } else {
                cp_wait0();
            }
            __syncthreads();

            const float* bufp = sE + (ch & 1) * 16384;
            const float* zrow = sZ + (w * 4) * ND + ch * 16;
#pragma unroll 4
            for (int kk = 0; kk < 16; ++kk) {
                float z0 = zrow[kk];
                float z1 = zrow[256 + kk];
                float z2 = zrow[512 + kk];
                float z3 = zrow[768 + kk];
                const float* er = bufp + kk * NK + lane;
#pragma unroll
                for (int j = 0; j < 32; ++j) {
                    float ev = er[j * 32];
                    acc[0][j] = fmaf(z0, ev, acc[0][j]);
                    acc[1][j] = fmaf(z1, ev, acc[1][j]);
                    acc[2][j] = fmaf(z2, ev, acc[2][j]);
                    acc[3][j] = fmaf(z3, ev, acc[3][j]);
                }
            }
            __syncthreads();
        }
#pragma unroll
        for (int i = 0; i < 4; ++i) {
            float* gp = &g_G[(size_t)(r0 + w * 4 + i) * NK];
#pragma unroll
            for (int j = 0; j < 32; ++j) gp[lane + 32 * j] = acc[i][j];
        }
        __syncthreads();
    }
#endif
}

// ---------------- k_soft: vectorized single-scan, 2 CTAs/SM ----------------
// Col mapping per row: lane owns float4 groups at cols 128k + 4*lane (k=0..7).
// Refinement dot product keeps the EXACT lane+32k scalar pattern of all
// passing rounds (do not reorder — one row has a true gap ~1e-6).
__global__ void __launch_bounds__(256, 2)
k_soft(const float* __restrict__ lat, const float* __restrict__ emb,
       float* __restrict__ out) {
    __shared__ float sX[8 * NK];
    __shared__ float s_mind[32];
    __shared__ int   s_idx[32];

    const int cta = blockIdx.x, row0 = cta * 32;
    const int tid = threadIdx.x, w = tid >> 5, lane = tid & 31;

    float4 csum[8];
#pragma unroll
    for (int k = 0; k < 8; ++k) csum[k] = make_float4(0.f, 0.f, 0.f, 0.f);

#pragma unroll 1
    for (int i = 0; i < 4; ++i) {
        const int r = row0 + w * 4 + i;
        const float* zr = lat + (size_t)r * ND;
        const float4* gr4 = (const float4*)(g_G + (size_t)r * NK);

        // zz (order-insensitive: uniform shift cancels in all decisions)
        float4 za = ((const float4*)zr)[lane];
        float4 zb = ((const float4*)zr)[lane + 32];
        float zz = za.x * za.x + za.y * za.y + za.z * za.z + za.w * za.w
                 + zb.x * zb.x + zb.y * zb.y + zb.z * zb.z + zb.w * zb.w;
#pragma unroll
        for (int off = 16; off; off >>= 1) zz += __shfl_xor_sync(0xffffffffu, zz, off);

        // dist (vectorized) + dmin
        float4 d4[8];
        float dmin = 3.4e38f;
#pragma unroll
        for (int k = 0; k < 8; ++k) {
            float4 g = __ldg(&gr4[k * 32 + lane]);
            float4 e = __ldg(&((const float4*)g_ee)[k * 32 + lane]);
            float4 di;
            di.x = __fsub_rn(__fadd_rn(zz, e.x), __fmul_rn(2.0f, g.x));
            di.y = __fsub_rn(__fadd_rn(zz, e.y), __fmul_rn(2.0f, g.y));
            di.z = __fsub_rn(__fadd_rn(zz, e.z), __fmul_rn(2.0f, g.z));
            di.w = __fsub_rn(__fadd_rn(zz, e.w), __fmul_rn(2.0f, g.w));
            d4[k] = di;
            dmin = fminf(dmin, fminf(fminf(di.x, di.y), fminf(di.z, di.w)));
        }
#pragma unroll
        for (int off = 16; off; off >>= 1)
            dmin = fminf(dmin, __shfl_xor_sync(0xffffffffu, dmin, off));

        // exact-FFMA refinement (tensor dist error << 1e-4)
        {
            float thr = dmin + 1e-4f;
            float bd = 3.4e38f;
            int   bi = NK;
#pragma unroll 1
            for (int k = 0; k < 8; ++k) {
#pragma unroll
                for (int e = 0; e < 4; ++e) {
                    float de = (e == 0) ? d4[k].x : (e == 1) ? d4[k].y
                             : (e == 2) ? d4[k].z : d4[k].w;
                    unsigned m = __ballot_sync(0xffffffffu, de < thr);
                    while (m) {
                        int src = __ffs(m) - 1;
                        m &= m - 1;
                        int col = k * 128 + src * 4 + e;
                        const float* er = emb + (size_t)col * ND;
                        float s = 0.f;
#pragma unroll
                        for (int kk = 0; kk < 8; ++kk)
                            s = fmaf(zr[lane + 32 * kk], __ldg(&er[lane + 32 * kk]), s);
#pragma unroll
                        for (int off = 16; off; off >>= 1)
                            s += __shfl_xor_sync(0xffffffffu, s, off);
                        float dc = __fsub_rn(__fadd_rn(zz, __ldg(&g_ee[col])),
                                             __fmul_rn(2.0f, s));
                        if (dc < bd || (dc == bd && col < bi)) { bd = dc; bi = col; }
                    }
                }
            }
            if (lane == 0) { s_mind[w * 4 + i] = bd; s_idx[w * 4 + i] = bi; }
        }

        // softmax (in-register)
        float ssum = 0.f;
#pragma unroll
        for (int k = 0; k < 8; ++k) {
            d4[k].x = __expf(-10.0f * (d4[k].x - dmin)); ssum += d4[k].x;
            d4[k].y = __expf(-10.0f * (d4[k].y - dmin)); ssum += d4[k].y;
            d4[k].z = __expf(-10.0f * (d4[k].z - dmin)); ssum += d4[k].z;
            d4[k].w = __expf(-10.0f * (d4[k].w - dmin)); ssum += d4[k].w;
        }
#pragma unroll
        for (int off = 16; off; off >>= 1) ssum += __shfl_xor_sync(0xffffffffu, ssum, off);
        float rinv = 1.0f / ssum;

        // P write (STG.64: OFF_P only 8B-aligned) + csum accumulate
        float2* pout2 = (float2*)(out + OFF_P + (size_t)r * NK);
#pragma unroll
        for (int k = 0; k < 8; ++k) {
            float4 p = make_float4(d4[k].x * rinv, d4[k].y * rinv,
                                   d4[k].z * rinv, d4[k].w * rinv);
            pout2[k * 64 + lane * 2]     = make_float2(p.x, p.y);
            pout2[k * 64 + lane * 2 + 1] = make_float2(p.z, p.w);
            csum[k].x += p.x; csum[k].y += p.y;
            csum[k].z += p.z; csum[k].w += p.w;
        }
    }

#pragma unroll
    for (int k = 0; k < 8; ++k)
        ((float4*)&sX[w * NK])[k * 32 + lane] = csum[k];
    __syncthreads();

    {   // colsum across 8 warps -> g_pavg (vectorized: thread owns 4 cols)
        float4 s = make_float4(0.f, 0.f, 0.f, 0.f);
#pragma unroll
        for (int ww = 0; ww < 8; ++ww) {
            float4 v = ((const float4*)&sX[ww * NK])[tid];
            s.x += v.x; s.y += v.y; s.z += v.z; s.w += v.w;
        }
        ((float4*)&g_pavg[(size_t)cta * NK])[tid] = s;
    }
    if (tid == 0) {
        float s = 0.f;
        for (int r = 0; r < 32; ++r) s += s_mind[r];
        g_pmind[cta] = s;
    }
    if (tid < 32) out[OFF_IDX + row0 + tid] = (float)s_idx[tid];

    for (int i = tid; i < 32 * ND / 2; i += 256) {
        int r = i >> 7, d2 = i & 127;
        float2 v = ((const float2*)(emb + (size_t)s_idx[r] * ND))[d2];
        ((float2*)(out + OFF_HQ + (size_t)row0 * ND))[i] = v;
    }
}

// ---------------- GEMM2: Q = P @ emb (M=128/CTA, N=256, 64 K-blocks) -------
__global__ void __launch_bounds__(256, 2)
k_gemm2(const float* __restrict__ lat,
        const __grid_constant__ CUtensorMap tmB,
        const float* __restrict__ emb, float* __restrict__ out) {
    (void)emb;
#if HAS_TC
    extern __shared__ char smem[];
    uint32_t sbase = smem_u32(smem);
    const int tid = threadIdx.x, wid = tid >> 5;
    const int row0 = blockIdx.x * 128;

    if (wid == 0) { TC_ALLOC(sbase, 256); TC_RELINQ(); }
    if (tid == 0)
        for (int b = 0; b < 2; ++b) {
            MBAR_INIT(sbase + MB_MMA + b * 8, 1);
            MBAR_INIT(sbase + MB_TMA + b * 8, 1);
        }
    __syncthreads();
    uint32_t tmem;
    asm volatile("ld.shared.b32 %0, [%1];" : "=r"(tmem) : "r"(sbase));

    const float* pbase = out + OFF_P + (size_t)row0 * NK;

    auto prep_load = [&](int gp, float4* v) {
#pragma unroll
        for (int it = 0; it < 2; ++it) {
            int t = tid + it * 256;
            int r = t >> 2, c4 = t & 3;
            const float* src = pbase + (size_t)r * NK + gp * 16 + c4 * 4;
            float2 v01 = *(const float2*)(src);
            float2 v23 = *(const float2*)(src + 2);
            v[it] = make_float4(v01.x, v01.y, v23.x, v23.y);
        }
    };
    auto prep_storeA = [&](int gp, const float4* v) {
        char* st = smem + 1024 + (gp & 1) * STG_SZ;
#pragma unroll
        for (int it = 0; it < 2; ++it) {
            int t = tid + it * 256;
            int r = t >> 2, c4 = t & 3;
            float4 vv = v[it];
            float4 h = make_float4(tf32hi(vv.x), tf32hi(vv.y), tf32hi(vv.z), tf32hi(vv.w));
            float4 l = make_float4(__fsub_rn(vv.x, h.x), __fsub_rn(vv.y, h.y),
                                   __fsub_rn(vv.z, h.z), __fsub_rn(vv.w, h.w));
            *(float4*)(st + sw128(r * 128 + c4 * 16))      = h;
            *(float4*)(st + sw128(r * 128 + 64 + c4 * 16)) = l;
        }
        FENCE_PROXY();
    };
    auto issue_tma = [&](int gp) {
        if (tid == 0) {
            uint32_t mb = sbase + MB_TMA + (gp & 1) * 8;
            MBAR_EXPECT(mb, 32768u);
            tma2d(sbase + 1024 + (gp & 1) * STG_SZ + 16384, &tmB,
                  gp * 32, 0, mb);
        }
    };

    {   // prologue
        float4 v[2];
        prep_load(0, v); prep_storeA(0, v); issue_tma(0);
        prep_load(1, v); prep_storeA(1, v); issue_tma(1);
    }

    for (int g = 0; g < 64; ++g) {
        const bool doP = (g + 2 < 64);
        float4 pf[2];
        if (doP) prep_load(g + 2, pf);
        MBAR_WAIT(sbase + MB_TMA + (g & 1) * 8, (uint32_t)((g >> 1) & 1));
        __syncthreads();
        if (wid == 0) {
            if (elect1()) {
                uint32_t sa = sbase + 1024 + (g & 1) * STG_SZ;
                uint64_t ad = sdesc(sa);
                uint64_t bd = sdesc(sa + 16384);
#pragma unroll
                for (int i = 0; i < 6; ++i)
                    mma_tf32(tmem, ad + c_AO[i], bd + c_BO[i], IDESC_TF32_N256,
                             (g > 0) || (i > 0));
                TC_COMMIT(sbase + MB_MMA + (g & 1) * 8);
            }
        }
        MBAR_WAIT(sbase + MB_MMA + (g & 1) * 8, (uint32_t)((g >> 1) & 1));
        if (doP) { prep_storeA(g + 2, pf); issue_tma(g + 2); }
    }
    TC_FENCE_AFTER();

    // epilogue: D[128 lanes][256 cols] -> q, loss partial
    {
        int wg = tid >> 7, w4 = (tid >> 5) & 3, lane = tid & 31;
        int row = row0 + w4 * 32 + lane;
        float lp = 0.f;
#pragma unroll 1
        for (int b = 0; b < 4; ++b) {
            uint32_t r[32];
            LDTM32(r, tmem + wg * 128 + b * 32);
            TC_WAIT_LD();
            int cb = wg * 128 + b * 32;
            float4* qp = (float4*)(out + OFF_Q + (size_t)row * ND + cb);
            const float4* lt = (const float4*)(lat + (size_t)row * ND + cb);
#pragma unroll
            for (int c4 = 0; c4 < 8; ++c4) {
                float4 q = make_float4(__uint_as_float(r[c4 * 4 + 0]),
                                       __uint_as_float(r[c4 * 4 + 1]),
                                       __uint_as_float(r[c4 * 4 + 2]),
                                       __uint_as_float(r[c4 * 4 + 3]));
                float4 l = lt[c4];
                qp[c4] = q;
                float d0 = q.x - l.x, d1 = q.y - l.y, d2 = q.z - l.z, d3 = q.w - l.w;
                lp = fmaf(d0, d0, lp); lp = fmaf(d1, d1, lp);
                lp = fmaf(d2, d2, lp); lp = fmaf(d3, d3, lp);
            }
        }
        TC_FENCE_BEFORE();
#pragma unroll
        for (int off = 16; off; off >>= 1) lp += __shfl_xor_sync(0xffffffffu, lp, off);
        float* red = (float*)(smem + 80);
        if ((tid & 31) == 0) red[tid >> 5] = lp;
        __syncthreads();
        if (tid == 0) {
            float s = 0.f;
            for (int ww = 0; ww < 8; ++ww) s += red[ww];
            g_ploss[blockIdx.x] = s;
        }
    }
    if (tid == 0)
        for (int b = 0; b < 2; ++b) {
            MBAR_INVAL(sbase + MB_MMA + b * 8);
            MBAR_INVAL(sbase + MB_TMA + b * 8);
        }
    __syncthreads();
    if (wid == 0) TC_DEALLOC(tmem, 256);
#else
    // ---------------- FFMA fallback (R4 GEMM2 structure) ----------------
    extern __shared__ float smf[];
    float* sE  = smf;
    float* sPb = smf + 16384;
    __shared__ float red8[8];
    const int tid = threadIdx.x, w = tid >> 5, lane = tid & 31;
    const int row0 = blockIdx.x * 128;
    float lsum = 0.f;

    for (int st = 0; st < 4; ++st) {
        const int r0 = row0 + st * 32;
        const float* pbase = out + OFF_P + (size_t)r0 * NK;

        float qacc[4][8];
#pragma unroll
        for (int i = 0; i < 4; ++i)
#pragma unroll
            for (int m = 0; m < 8; ++m) qacc[i][m] = 0.f;

        for (int i = tid; i < 2048; i += 256) cp16(sE + i * 4, emb + i * 4);
        cp_commit();

#pragma unroll 1
        for (int ch = 0; ch < 32; ++ch) {
            if (ch < 31) {
                const float* src = emb + (size_t)(ch + 1) * 32 * ND;
                float* dst = sE + ((ch + 1) & 1) * 8192;
                for (int i = tid; i < 2048; i += 256) cp16(dst + i * 4, src + i * 4);
                cp_commit();
                cp_wait1();
            } else {
                cp_wait0();
            }
            __syncthreads();
            for (int i = tid; i < 1024; i += 256) {
                int r = i >> 5, c = i & 31;
                sPb[i] = pbase[(size_t)r * NK + ch * 32 + c];
            }
            __syncthreads();

            const float* bp = sE + (ch & 1) * 8192;
#pragma unroll 4
            for (int c = 0; c < 32; ++c) {
                float p0 = sPb[(w * 4 + 0) * 32 + c];
                float p1 = sPb[(w * 4 + 1) * 32 + c];
                float p2 = sPb[(w * 4 + 2) * 32 + c];
                float p3 = sPb[(w * 4 + 3) * 32 + c];
                const float* er = bp + c * ND + lane;
#pragma unroll
                for (int m = 0; m < 8; ++m) {
                    float ev = er[32 * m];
                    qacc[0][m] = fmaf(p0, ev, qacc[0][m]);
                    qacc[1][m] = fmaf(p1, ev, qacc[1][m]);
                    qacc[2][m] = fmaf(p2, ev, qacc[2][m]);
                    qacc[3][m] = fmaf(p3, ev, qacc[3][m]);
                }
            }
            __syncthreads();
        }
#pragma unroll
        for (int i = 0; i < 4; ++i) {
            int row = r0 + w * 4 + i;
#pragma unroll
            for (int m = 0; m < 8; ++m) {
                int d = lane + 32 * m;
                float qv = qacc[i][m];
                out[OFF_Q + (size_t)row * ND + d] = qv;
                float dz = qv - lat[(size_t)row * ND + d];
                lsum = fmaf(dz, dz, lsum);
            }
        }
        __syncthreads();
    }
#pragma unroll
    for (int off = 16; off; off >>= 1) lsum += __shfl_xor_sync(0xffffffffu, lsum, off);
    if (lane == 0) red8[w] = lsum;
    __syncthreads();
    if (tid == 0) {
        float s = 0.f;
        for (int ww = 0; ww < 8; ++ww) s += red8[ww];
        g_ploss[blockIdx.x] = s;
    }
#endif
}

// ---------------- stage-2 avg_probs reduction ----------------
__global__ void k_red() {
    int g = blockIdx.x;
    for (int c = threadIdx.x; c < NK; c += 256) {
        float s = 0.f;
        for (int r = 0; r < 64; ++r) s += g_pavg[(size_t)(g * 64 + r) * NK + c];
        g_pavg2[g * NK + c] = s;
    }
}

// ---------------- finalize scalars ----------------
__global__ void k_fin(float* __restrict__ out) {
    __shared__ float red[1024];
    int t = threadIdx.x;

    float a = 0.f;
    for (int gg = 0; gg < 32; ++gg) a += g_pavg2[gg * NK + t];
    a *= (1.0f / 65536.0f);
    red[t] = -a * logf(a + 1e-10f);
    __syncthreads();
    for (int s = 512; s; s >>= 1) { if (t < s) red[t] += red[t + s]; __syncthreads(); }
    float ent = red[0];
    __syncthreads();

    red[t] = (t < 512) ? g_ploss[t] : 0.f;
    __syncthreads();
    for (int s = 512; s; s >>= 1) { if (t < s) red[t] += red[t + s]; __syncthreads(); }
    float mse = red[0] * (1.0f / 16777216.0f);
    float vq  = __fadd_rn(__fmul_rn(mse, 0.25f), mse);
    __syncthreads();

    red[t] = g_pmind[t] + g_pmind[t + 1024];
    __syncthreads();
    for (int s = 512; s; s >>= 1) { if (t < s) red[t] += red[t + s]; __syncthreads(); }
    float cm = red[0] * (1.0f / 65536.0f);

    if (t == 0) {
        out[OFF_VQ]  = vq;
        out[OFF_ENT] = ent;
        out[OFF_CM]  = cm;
    }
}

// ---------------- host: tensormap construction ----------------
typedef CUresult (*EncodeFn)(CUtensorMap*, CUtensorMapDataType, cuuint32_t,
                             void*, const cuuint64_t*, const cuuint64_t*,
                             const cuuint32_t*, const cuuint32_t*,
                             CUtensorMapInterleave, CUtensorMapSwizzle,
                             CUtensorMapL2promotion, CUtensorMapFloatOOBfill);

static void make_map(EncodeFn enc, CUtensorMap* m, void* ptr,
                     unsigned long long d0, unsigned long long d1,
                     unsigned long long stride_bytes) {
    cuuint64_t dims[2] = {d0, d1};
    cuuint64_t str[1]  = {stride_bytes};
    cuuint32_t box[2]  = {32u, 256u};
    cuuint32_t es[2]   = {1u, 1u};
    enc(m, CU_TENSOR_MAP_DATA_TYPE_FLOAT32, 2, ptr, dims, str, box, es,
        CU_TENSOR_MAP_INTERLEAVE_NONE, CU_TENSOR_MAP_SWIZZLE_128B,
        CU_TENSOR_MAP_L2_PROMOTION_L2_128B, CU_TENSOR_MAP_FLOAT_OOB_FILL_NONE);
}

// ---------------- launch ----------------
extern "C" void kernel_launch(void* const* d_in, const int* in_sizes, int n_in,
                              void* d_out, int out_size) {
    const float* lat = (const float*)d_in[0];
    const float* emb = (const float*)d_in[1];
    float* out = (float*)d_out;

    void* fp = nullptr;
    cudaDriverEntryPointQueryResult qr;
    cudaGetDriverEntryPoint("cuTensorMapEncodeTiled", &fp, cudaEnableDefault, &qr);
    EncodeFn enc = (EncodeFn)fp;

    void *pEmbI = nullptr, *pEmbTI = nullptr;
    cudaGetSymbolAddress(&pEmbI, g_embI);
    cudaGetSymbolAddress(&pEmbTI, g_embTI);

    CUtensorMap m1, m2;
    make_map(enc, &m1, pEmbI, 512, 1024, 512ull * 4ull);
    make_map(enc, &m2, pEmbTI, 2048, 256, 2048ull * 4ull);

    cudaFuncSetAttribute(k_gemm1, cudaFuncAttributeMaxDynamicSharedMemorySize, G_SMEM);
    cudaFuncSetAttribute(k_gemm2, cudaFuncAttributeMaxDynamicSharedMemorySize, G_SMEM);

    k_prep2<<<1024, 256>>>(emb);
    k_ee<<<4, 256>>>(emb);
    k_nop<<<1, 32>>>();                 // keeps k_gemm1 at launch #4 for ncu
    k_gemm1<<<512, 256, G_SMEM>>>(lat, m1);
    k_soft<<<2048, 256>>>(lat, emb, out);
    k_gemm2<<<512, 256, G_SMEM>>>(lat, m2, emb, out);
    k_red<<<32, 256>>>();
    k_fin<<<1, 1024>>>(out);
}